// round 10
// baseline (speedup 1.0000x reference)
#include <cuda_runtime.h>
#include <stdint.h>

// ---------------- problem constants ----------------
// SPARSE_SHAPE (468,468,1), WINDOW (12,12,1), BATCH 4
// _NX=_NY=40, _NZ=2 ; win_z==0 always ; full_win = 2*compact
// compact win id = b*1600 + wx*40 + wy  in [0, 6400)
#define NWc   6400
#define CAP   512               // max voxels per window (uniform data: ~49 mean)
#define MAXN  327680
#define FULLM 0xFFFFFFFFu

// ---------------- static scratch (no allocations allowed) -------------------
__device__ int           g_cnt0[NWc];
__device__ int           g_cnt1[NWc];
__device__ int           g_bkt0[NWc * CAP];   // voxel indices per window, round 0
__device__ int           g_bkt1[NWc * CAP];   // round 1
__device__ int           g_winc0[MAXN];
__device__ int           g_winc1[MAXN];
__device__ int           g_inner0[MAXN];
__device__ int           g_inner1[MAXN];
__device__ unsigned char g_keep0[MAXN];
__device__ unsigned char g_keepF[MAXN];

__device__ __forceinline__ void lvl_target(int n, int& lvl, int& target) {
    if (n < 16)      { lvl = 0; target = 16; }
    else if (n < 32) { lvl = 1; target = 32; }
    else if (n < 64) { lvl = 2; target = 64; }
    else             { lvl = 3; target = 144; }
}

// ---------------- phase 0: zero the 2x6400 window counters ------------------
__global__ void k_zerocnt() {
    int i = blockIdx.x * blockDim.x + threadIdx.x;
    if (i < NWc) { g_cnt0[i] = 0; g_cnt1[i] = 0; }
}

// ---------------- phase 1: window ids + bucket scatter (round 0) ------------
__global__ void k_scatter0(const int* __restrict__ coords, int N) {
    for (int i = blockIdx.x * blockDim.x + threadIdx.x; i < N;
         i += gridDim.x * blockDim.x) {
        int4 cc = ((const int4*)coords)[i];          // (b,z,y,x)
        int b = cc.x, y = cc.z, x = cc.w;
        int w0 = b * 1600 + ((x + 12) / 12) * 40 + ((y + 12) / 12);
        int w1 = b * 1600 + ((x + 6)  / 12) * 40 + ((y + 6)  / 12);
        g_winc0[i] = w0;
        g_winc1[i] = w1;
        int pos = atomicAdd(&g_cnt0[w0], 1);
        if (pos < CAP) g_bkt0[w0 * CAP + pos] = i;
    }
}

// ---------------- phase 2: rank round 0 + inline scatter to round-1 buckets -
// rank of element = number of bucket entries with smaller voxel index (stable).
__global__ void __launch_bounds__(128)
k_wrank0s1() {
    __shared__ int s[CAP];
    int w = blockIdx.x;
    int n = g_cnt0[w];
    if (n > CAP) n = CAP;
    for (int t = threadIdx.x; t < n; t += 128) s[t] = g_bkt0[w * CAP + t];
    __syncthreads();
    int lvl, target; lvl_target(n, lvl, target);
    for (int e = threadIdx.x; e < n; e += 128) {
        int my = s[e];
        int r = 0;
        for (int j = 0; j < n; j++) r += (s[j] < my);
        g_inner0[my] = r;
        int kp = (r < target);
        g_keep0[my] = kp;
        if (kp) {
            int w1 = g_winc1[my];
            int pos = atomicAdd(&g_cnt1[w1], 1);
            if (pos < CAP) g_bkt1[w1 * CAP + pos] = my;
        } else {
            g_inner1[my] = -1;
            g_keepF[my]  = 0;
        }
    }
}

// ---------------- phase 3: per-window stable rank (round 1) -----------------
__global__ void __launch_bounds__(128)
k_wrank1() {
    __shared__ int s[CAP];
    int w = blockIdx.x;
    int n = g_cnt1[w];
    if (n > CAP) n = CAP;
    for (int t = threadIdx.x; t < n; t += 128) s[t] = g_bkt1[w * CAP + t];
    __syncthreads();
    int lvl, target; lvl_target(n, lvl, target);
    for (int e = threadIdx.x; e < n; e += 128) {
        int my = s[e];
        int r = 0;
        for (int j = 0; j < n; j++) r += (s[j] < my);
        g_inner1[my] = r;
        g_keepF[my]  = (r < target) ? 1 : 0;
    }
}

// ---------------- phase 4a: scalar output vectors (flat, non-divergent) -----
__global__ void k_outvec(float* __restrict__ out, int N,
                         size_t off_keep, size_t off_w0, size_t off_w1,
                         size_t off_dl0, size_t off_dl1,
                         size_t off_i0, size_t off_i1) {
    for (int i = blockIdx.x * blockDim.x + threadIdx.x; i < N;
         i += gridDim.x * blockDim.x) {
        int w0 = g_winc0[i], w1 = g_winc1[i];
        out[off_keep + i] = g_keepF[i] ? 1.0f : 0.0f;
        out[off_w0 + i]   = (float)(2 * w0);
        out[off_w1 + i]   = (float)(2 * w1);
        int l0, t0; lvl_target(g_cnt0[w0], l0, t0);
        out[off_dl0 + i] = (float)l0;
        float dl1 = -1.0f;
        if (g_keep0[i]) {
            int l1, t1; lvl_target(g_cnt1[w1], l1, t1);
            dl1 = (float)l1;
        }
        out[off_dl1 + i] = dl1;
        out[off_i0 + i] = (float)g_inner0[i];
        out[off_i1 + i] = (float)g_inner1[i];
    }
}

// ---------------- phase 4b: masked features (float4 streamed) ---------------
__global__ void __launch_bounds__(256)
k_featmask(const float* __restrict__ feat, float* __restrict__ out, long total4, int C4) {
    for (long t = (long)blockIdx.x * blockDim.x + threadIdx.x; t < total4;
         t += (long)gridDim.x * blockDim.x) {
        long i = t / C4;                       // row
        float kf = g_keepF[i] ? 1.0f : 0.0f;
        float4 v = ((const float4*)feat)[t];
        v.x *= kf; v.y *= kf; v.z *= kf; v.w *= kf;
        ((float4*)out)[t] = v;
    }
}

// ---------------- independent branch: positional embeddings (coords only) ---
// OCCUPANCY-CAPPED: grid 592 = 4 blocks/SM = 512 threads/SM, leaving 3/4 of
// each SM's thread slots free so the concurrent rank chain can co-schedule.
// Store-dominated: ~500 independent iterations/block keep BW saturated.
__global__ void __launch_bounds__(128)
k_pe(const int* __restrict__ coords, float* __restrict__ out, int N, int C,
     size_t off_pe0, size_t off_pe1) {
    int cidx = threadIdx.x;           // 0..C-1 (C=128)
    int half = C >> 1;                // 64
    bool isy = cidx >= half;
    int j = (isy ? (cidx - half) : cidx) >> 1;        // freq index 0..31
    bool iscos = (cidx & 1);
    // 1/inv_freq = 10000^(-(2j)/(C/2)) = 2^(-j * 4*log2(1e4)/C)
    float rec = exp2f(-(float)j * (13.28771237954944987f * 4.0f / (float)C));

    for (int i = blockIdx.x; i < N; i += gridDim.x) {
        int x = __ldg(&coords[i * 4 + 3]);
        int y = __ldg(&coords[i * 4 + 2]);
        int v = isy ? y : x;
        float v0 = (float)(v % 12) - 6.0f;            // unshifted in-window coord - w/2
        float v1 = (float)((v + 6) % 12) - 6.0f;      // shifted
        float a0 = v0 * rec, a1 = v1 * rec;
        size_t row = (size_t)i * C + cidx;
        out[off_pe0 + row] = iscos ? __cosf(a0) : __sinf(a0);
        out[off_pe1 + row] = iscos ? __cosf(a1) : __sinf(a1);
    }
}

// ---------------- launch ----------------
extern "C" void kernel_launch(void* const* d_in, const int* in_sizes, int n_in,
                              void* d_out, int out_size) {
    const float* feat   = (const float*)d_in[0];
    const int*   coords = (const int*)d_in[1];
    int N = in_sizes[1] / 4;
    int C = in_sizes[0] / N;          // 128
    if (N > MAXN) N = MAXN;           // safety (setup gives exactly 300000)

    float* out = (float*)d_out;
    size_t Ns = (size_t)N, Cs = (size_t)C;
    size_t off = Ns * Cs;             // feat at 0
    size_t off_keep = off; off += Ns;
    size_t off_w0   = off; off += Ns;
    size_t off_w1   = off; off += Ns;
    size_t off_dl0  = off; off += Ns;
    size_t off_dl1  = off; off += Ns;
    size_t off_i0   = off; off += Ns;
    size_t off_i1   = off; off += Ns;
    size_t off_pe0  = off; off += Ns * Cs;
    size_t off_pe1  = off;

    // Fork: PE branch depends only on coords. s2 gets LOW priority so its
    // pending blocks yield launch slots to the latency-bound rank chain.
    int prLow = 0, prHigh = 0;
    cudaDeviceGetStreamPriorityRange(&prLow, &prHigh);   // prLow = numerically largest
    cudaStream_t s2;
    cudaStreamCreateWithPriority(&s2, cudaStreamNonBlocking, prLow);
    cudaEvent_t eFork, eJoin;
    cudaEventCreateWithFlags(&eFork, cudaEventDisableTiming);
    cudaEventCreateWithFlags(&eJoin, cudaEventDisableTiming);

    cudaEventRecord(eFork, 0);
    cudaStreamWaitEvent(s2, eFork, 0);

    // branch B (s2): positional embeddings, occupancy-capped
    k_pe<<<592, 128, 0, s2>>>(coords, out, N, C, off_pe0, off_pe1);

    // branch A (main): latency-bound rank chain + dependent outputs
    k_zerocnt<<<(NWc + 255) / 256, 256>>>();
    k_scatter0<<<592, 256>>>(coords, N);
    k_wrank0s1<<<NWc, 128>>>();
    k_wrank1<<<NWc, 128>>>();
    k_outvec<<<512, 256>>>(out, N, off_keep, off_w0, off_w1,
                           off_dl0, off_dl1, off_i0, off_i1);
    long total4 = (long)Ns * Cs / 4;
    k_featmask<<<1184, 256>>>(feat, out, total4, C / 4);

    cudaEventRecord(eJoin, s2);
    cudaStreamWaitEvent(0, eJoin, 0);   // join
    // s2/events deliberately not destroyed: destroying capture-participating
    // resources invalidates the graph; kernel_launch runs only a few times.
}

// round 11
// speedup vs baseline: 1.8997x; 1.8997x over previous
#include <cuda_runtime.h>
#include <stdint.h>

// ---------------- problem constants ----------------
// SPARSE_SHAPE (468,468,1), WINDOW (12,12,1), BATCH 4
// _NX=_NY=40, _NZ=2 ; win_z==0 always ; full_win = 2*compact
// compact win id = b*1600 + wx*40 + wy  in [0, 6400)
#define NWc   6400
#define CAP   512               // max voxels per window (uniform data: ~49 mean)
#define MAXN  327680
#define FULLM 0xFFFFFFFFu

// ---------------- static scratch (no allocations allowed) -------------------
__device__ int           g_cnt0[NWc];
__device__ int           g_cnt1[NWc];
__device__ int           g_bkt0[NWc * CAP];   // voxel indices per window, round 0
__device__ int           g_bkt1[NWc * CAP];   // round 1
__device__ int           g_winc0[MAXN];
__device__ int           g_winc1[MAXN];
__device__ int           g_inner0[MAXN];
__device__ int           g_inner1[MAXN];
__device__ unsigned char g_keep0[MAXN];
__device__ unsigned char g_keepF[MAXN];

__device__ __forceinline__ void lvl_target(int n, int& lvl, int& target) {
    if (n < 16)      { lvl = 0; target = 16; }
    else if (n < 32) { lvl = 1; target = 32; }
    else if (n < 64) { lvl = 2; target = 64; }
    else             { lvl = 3; target = 144; }
}

// ---------------- phase 0: zero the 2x6400 window counters ------------------
__global__ void k_zerocnt() {
    int i = blockIdx.x * blockDim.x + threadIdx.x;
    if (i < NWc) { g_cnt0[i] = 0; g_cnt1[i] = 0; }
}

// ---------------- phase 1: window ids + bucket scatter (round 0) ------------
__global__ void k_scatter0(const int* __restrict__ coords, int N) {
    for (int i = blockIdx.x * blockDim.x + threadIdx.x; i < N;
         i += gridDim.x * blockDim.x) {
        int4 cc = ((const int4*)coords)[i];          // (b,z,y,x)
        int b = cc.x, y = cc.z, x = cc.w;
        int w0 = b * 1600 + ((x + 12) / 12) * 40 + ((y + 12) / 12);
        int w1 = b * 1600 + ((x + 6)  / 12) * 40 + ((y + 6)  / 12);
        g_winc0[i] = w0;
        g_winc1[i] = w1;
        int pos = atomicAdd(&g_cnt0[w0], 1);
        if (pos < CAP) g_bkt0[w0 * CAP + pos] = i;
    }
}

// ---------------- phase 2: rank round 0 + inline scatter to round-1 buckets -
// rank of element = number of bucket entries with smaller voxel index (stable).
__global__ void __launch_bounds__(128)
k_wrank0s1() {
    __shared__ int s[CAP];
    int w = blockIdx.x;
    int n = g_cnt0[w];
    if (n > CAP) n = CAP;
    for (int t = threadIdx.x; t < n; t += 128) s[t] = g_bkt0[w * CAP + t];
    __syncthreads();
    int lvl, target; lvl_target(n, lvl, target);
    for (int e = threadIdx.x; e < n; e += 128) {
        int my = s[e];
        int r = 0;
        for (int j = 0; j < n; j++) r += (s[j] < my);
        g_inner0[my] = r;
        int kp = (r < target);
        g_keep0[my] = kp;
        if (kp) {
            int w1 = g_winc1[my];
            int pos = atomicAdd(&g_cnt1[w1], 1);
            if (pos < CAP) g_bkt1[w1 * CAP + pos] = my;
        } else {
            g_inner1[my] = -1;
            g_keepF[my]  = 0;
        }
    }
}

// ---------------- phase 3: per-window stable rank (round 1) -----------------
__global__ void __launch_bounds__(128)
k_wrank1() {
    __shared__ int s[CAP];
    int w = blockIdx.x;
    int n = g_cnt1[w];
    if (n > CAP) n = CAP;
    for (int t = threadIdx.x; t < n; t += 128) s[t] = g_bkt1[w * CAP + t];
    __syncthreads();
    int lvl, target; lvl_target(n, lvl, target);
    for (int e = threadIdx.x; e < n; e += 128) {
        int my = s[e];
        int r = 0;
        for (int j = 0; j < n; j++) r += (s[j] < my);
        g_inner1[my] = r;
        g_keepF[my]  = (r < target) ? 1 : 0;
    }
}

// ---------------- phase 4a: scalar output vectors (flat, non-divergent) -----
__global__ void k_outvec(float* __restrict__ out, int N,
                         size_t off_keep, size_t off_w0, size_t off_w1,
                         size_t off_dl0, size_t off_dl1,
                         size_t off_i0, size_t off_i1) {
    for (int i = blockIdx.x * blockDim.x + threadIdx.x; i < N;
         i += gridDim.x * blockDim.x) {
        int w0 = g_winc0[i], w1 = g_winc1[i];
        out[off_keep + i] = g_keepF[i] ? 1.0f : 0.0f;
        out[off_w0 + i]   = (float)(2 * w0);
        out[off_w1 + i]   = (float)(2 * w1);
        int l0, t0; lvl_target(g_cnt0[w0], l0, t0);
        out[off_dl0 + i] = (float)l0;
        float dl1 = -1.0f;
        if (g_keep0[i]) {
            int l1, t1; lvl_target(g_cnt1[w1], l1, t1);
            dl1 = (float)l1;
        }
        out[off_dl1 + i] = dl1;
        out[off_i0 + i] = (float)g_inner0[i];
        out[off_i1 + i] = (float)g_inner1[i];
    }
}

// ---------------- phase 4b: masked features + PE via smem LUT ---------------
// PE values take only 12x64 distinct values: TT[v][c64] = trig((v-6)*rec(j)),
// v = coordinate mod 12. Build the 3KB table once per block (768 sin/cos),
// then the row loop is pure LDS + STG — no MUFU in the hot path.
__global__ void __launch_bounds__(128)
k_outfeat(const float* __restrict__ feat, const int* __restrict__ coords,
          float* __restrict__ out, int N, int C,
          size_t off_pe0, size_t off_pe1) {
    __shared__ float TT[12 * 64];     // [v][c64]
    int cidx = threadIdx.x;           // 0..127
    int half = C >> 1;                // 64
    bool isy = cidx >= half;

    // build LUT: entry e = v*64 + c64 ; value = (c64&1 ? cos : sin)((v-6)*rec)
    for (int e = cidx; e < 12 * 64; e += 128) {
        int v   = e >> 6;
        int c64 = e & 63;
        int j   = c64 >> 1;
        float rec = exp2f(-(float)j * (13.28771237954944987f * 4.0f / (float)C));
        float a = ((float)v - 6.0f) * rec;
        TT[e] = (c64 & 1) ? __cosf(a) : __sinf(a);
    }
    __syncthreads();

    int c64 = cidx & 63;              // channel within half
    for (int i = blockIdx.x; i < N; i += gridDim.x) {
        int x = __ldg(&coords[i * 4 + 3]);
        int y = __ldg(&coords[i * 4 + 2]);
        float kf = g_keepF[i] ? 1.0f : 0.0f;
        size_t row = (size_t)i * C + cidx;
        out[row] = feat[row] * kf;

        int v  = isy ? y : x;
        int v0 = v % 12;              // unshifted in-window coord
        int v1 = v0 + 6; if (v1 >= 12) v1 -= 12;   // (v+6)%12
        out[off_pe0 + row] = TT[v0 * 64 + c64];
        out[off_pe1 + row] = TT[v1 * 64 + c64];
    }
}

// ---------------- launch ----------------
extern "C" void kernel_launch(void* const* d_in, const int* in_sizes, int n_in,
                              void* d_out, int out_size) {
    const float* feat   = (const float*)d_in[0];
    const int*   coords = (const int*)d_in[1];
    int N = in_sizes[1] / 4;
    int C = in_sizes[0] / N;          // 128
    if (N > MAXN) N = MAXN;           // safety (setup gives exactly 300000)

    float* out = (float*)d_out;
    size_t Ns = (size_t)N, Cs = (size_t)C;
    size_t off = Ns * Cs;             // feat at 0
    size_t off_keep = off; off += Ns;
    size_t off_w0   = off; off += Ns;
    size_t off_w1   = off; off += Ns;
    size_t off_dl0  = off; off += Ns;
    size_t off_dl1  = off; off += Ns;
    size_t off_i0   = off; off += Ns;
    size_t off_i1   = off; off += Ns;
    size_t off_pe0  = off; off += Ns * Cs;
    size_t off_pe1  = off;

    k_zerocnt<<<(NWc + 255) / 256, 256>>>();
    k_scatter0<<<592, 256>>>(coords, N);
    k_wrank0s1<<<NWc, 128>>>();
    k_wrank1<<<NWc, 128>>>();
    k_outvec<<<512, 256>>>(out, N, off_keep, off_w0, off_w1,
                           off_dl0, off_dl1, off_i0, off_i1);
    k_outfeat<<<2368, 128>>>(feat, coords, out, N, C, off_pe0, off_pe1);
}

// round 12
// speedup vs baseline: 2.0212x; 1.0640x over previous
#include <cuda_runtime.h>
#include <stdint.h>

// ---------------- problem constants ----------------
// SPARSE_SHAPE (468,468,1), WINDOW (12,12,1), BATCH 4
// _NX=_NY=40, _NZ=2 ; win_z==0 always ; full_win = 2*compact
// compact win id = b*1600 + wx*40 + wy  in [0, 6400)
#define NWc   6400
#define CAP   512               // max voxels per window (uniform data: ~49 mean)
#define MAXN  327680
#define FULLM 0xFFFFFFFFu

// ---------------- static scratch (no allocations allowed) -------------------
__device__ int           g_cnt0[NWc];
__device__ int           g_cnt1[NWc];
__device__ int           g_bkt0[NWc * CAP];   // voxel indices per window, round 0
__device__ int           g_bkt1[NWc * CAP];   // round 1
__device__ int           g_winc0[MAXN];
__device__ int           g_winc1[MAXN];
__device__ int           g_inner0[MAXN];
__device__ int           g_inner1[MAXN];
__device__ unsigned char g_keep0[MAXN];
__device__ unsigned char g_keepF[MAXN];

__device__ __forceinline__ void lvl_target(int n, int& lvl, int& target) {
    if (n < 16)      { lvl = 0; target = 16; }
    else if (n < 32) { lvl = 1; target = 32; }
    else if (n < 64) { lvl = 2; target = 64; }
    else             { lvl = 3; target = 144; }
}

// ---------------- phase 0: zero the 2x6400 window counters ------------------
__global__ void k_zerocnt() {
    int i = blockIdx.x * blockDim.x + threadIdx.x;
    if (i < NWc) { g_cnt0[i] = 0; g_cnt1[i] = 0; }
}

// ---------------- phase 1: window ids + bucket scatter (round 0) ------------
__global__ void k_scatter0(const int* __restrict__ coords, int N) {
    for (int i = blockIdx.x * blockDim.x + threadIdx.x; i < N;
         i += gridDim.x * blockDim.x) {
        int4 cc = ((const int4*)coords)[i];          // (b,z,y,x)
        int b = cc.x, y = cc.z, x = cc.w;
        int w0 = b * 1600 + ((x + 12) / 12) * 40 + ((y + 12) / 12);
        int w1 = b * 1600 + ((x + 6)  / 12) * 40 + ((y + 6)  / 12);
        g_winc0[i] = w0;
        g_winc1[i] = w1;
        int pos = atomicAdd(&g_cnt0[w0], 1);
        if (pos < CAP) g_bkt0[w0 * CAP + pos] = i;
    }
}

// ---------------- phase 2: rank round 0 + inline scatter to round-1 buckets -
// rank of element = number of bucket entries with smaller voxel index (stable).
// 64 threads/block: mean window population ~49, so 128-thread blocks idled
// half their threads; smaller blocks double residency for latency hiding.
__global__ void __launch_bounds__(64)
k_wrank0s1() {
    __shared__ int s[CAP];
    int w = blockIdx.x;
    int n = g_cnt0[w];
    if (n > CAP) n = CAP;
    for (int t = threadIdx.x; t < n; t += 64) s[t] = g_bkt0[w * CAP + t];
    __syncthreads();
    int lvl, target; lvl_target(n, lvl, target);
    for (int e = threadIdx.x; e < n; e += 64) {
        int my = s[e];
        int r = 0;
        for (int j = 0; j < n; j++) r += (s[j] < my);
        g_inner0[my] = r;
        int kp = (r < target);
        g_keep0[my] = kp;
        if (kp) {
            int w1 = g_winc1[my];
            int pos = atomicAdd(&g_cnt1[w1], 1);
            if (pos < CAP) g_bkt1[w1 * CAP + pos] = my;
        } else {
            g_inner1[my] = -1;
            g_keepF[my]  = 0;
        }
    }
}

// ---------------- phase 3: per-window stable rank (round 1) -----------------
__global__ void __launch_bounds__(64)
k_wrank1() {
    __shared__ int s[CAP];
    int w = blockIdx.x;
    int n = g_cnt1[w];
    if (n > CAP) n = CAP;
    for (int t = threadIdx.x; t < n; t += 64) s[t] = g_bkt1[w * CAP + t];
    __syncthreads();
    int lvl, target; lvl_target(n, lvl, target);
    for (int e = threadIdx.x; e < n; e += 64) {
        int my = s[e];
        int r = 0;
        for (int j = 0; j < n; j++) r += (s[j] < my);
        g_inner1[my] = r;
        g_keepF[my]  = (r < target) ? 1 : 0;
    }
}

// ---------------- phase 4a: scalar output vectors (flat, non-divergent) -----
__global__ void k_outvec(float* __restrict__ out, int N,
                         size_t off_keep, size_t off_w0, size_t off_w1,
                         size_t off_dl0, size_t off_dl1,
                         size_t off_i0, size_t off_i1) {
    for (int i = blockIdx.x * blockDim.x + threadIdx.x; i < N;
         i += gridDim.x * blockDim.x) {
        int w0 = g_winc0[i], w1 = g_winc1[i];
        out[off_keep + i] = g_keepF[i] ? 1.0f : 0.0f;
        out[off_w0 + i]   = (float)(2 * w0);
        out[off_w1 + i]   = (float)(2 * w1);
        int l0, t0; lvl_target(g_cnt0[w0], l0, t0);
        out[off_dl0 + i] = (float)l0;
        float dl1 = -1.0f;
        if (g_keep0[i]) {
            int l1, t1; lvl_target(g_cnt1[w1], l1, t1);
            dl1 = (float)l1;
        }
        out[off_dl1 + i] = dl1;
        out[off_i0 + i] = (float)g_inner0[i];
        out[off_i1 + i] = (float)g_inner1[i];
    }
}

// ---------------- helper: build the 12x64 PE LUT ----------------------------
__device__ __forceinline__ void build_pe_lut(float* TT, int tid, int nthr, int C) {
    for (int e = tid; e < 12 * 64; e += nthr) {
        int v   = e >> 6;
        int c64 = e & 63;
        int j   = c64 >> 1;
        float rec = exp2f(-(float)j * (13.28771237954944987f * 4.0f / (float)C));
        float a = ((float)v - 6.0f) * rec;
        TT[e] = (c64 & 1) ? __cosf(a) : __sinf(a);
    }
}

// ---------------- phase 4b (vector): warp-per-row, float4 everywhere --------
// Lane l covers channels 4l..4l+3. All of feat read/store, pe0, pe1 are
// 128-bit ops: 4x fewer STG/LDS than the scalar version -> pure BW.
__global__ void __launch_bounds__(128)
k_outfeat_v4(const float* __restrict__ feat, const int* __restrict__ coords,
             float* __restrict__ out, int N, int C,
             size_t off_pe0, size_t off_pe1) {
    __shared__ float TT[12 * 64];
    build_pe_lut(TT, threadIdx.x, 128, C);
    __syncthreads();

    const float4* TT4 = (const float4*)TT;       // [12][16]
    int warp = threadIdx.x >> 5, lane = threadIdx.x & 31;
    int t = lane & 15;                           // float4 index within half

    for (int i = blockIdx.x * 4 + warp; i < N; i += gridDim.x * 4) {
        int x = __ldg(&coords[i * 4 + 3]);
        int y = __ldg(&coords[i * 4 + 2]);
        float kf = g_keepF[i] ? 1.0f : 0.0f;

        size_t row4 = (size_t)i * 32 + lane;     // float4 index into [N,128]
        float4 f = ((const float4*)feat)[row4];
        f.x *= kf; f.y *= kf; f.z *= kf; f.w *= kf;
        ((float4*)out)[row4] = f;

        int v  = (lane < 16) ? x : y;
        int v0 = v % 12;
        int v1 = v0 + 6; if (v1 >= 12) v1 -= 12;
        ((float4*)(out + off_pe0))[row4] = TT4[v0 * 16 + t];
        ((float4*)(out + off_pe1))[row4] = TT4[v1 * 16 + t];
    }
}

// ---------------- phase 4b (scalar fallback, N%4 != 0) ----------------------
__global__ void __launch_bounds__(128)
k_outfeat_s(const float* __restrict__ feat, const int* __restrict__ coords,
            float* __restrict__ out, int N, int C,
            size_t off_pe0, size_t off_pe1) {
    __shared__ float TT[12 * 64];
    build_pe_lut(TT, threadIdx.x, 128, C);
    __syncthreads();

    int cidx = threadIdx.x;
    int half = C >> 1;
    bool isy = cidx >= half;
    int c64 = cidx & 63;
    for (int i = blockIdx.x; i < N; i += gridDim.x) {
        int x = __ldg(&coords[i * 4 + 3]);
        int y = __ldg(&coords[i * 4 + 2]);
        float kf = g_keepF[i] ? 1.0f : 0.0f;
        size_t row = (size_t)i * C + cidx;
        out[row] = feat[row] * kf;
        int v  = isy ? y : x;
        int v0 = v % 12;
        int v1 = v0 + 6; if (v1 >= 12) v1 -= 12;
        out[off_pe0 + row] = TT[v0 * 64 + c64];
        out[off_pe1 + row] = TT[v1 * 64 + c64];
    }
}

// ---------------- launch ----------------
extern "C" void kernel_launch(void* const* d_in, const int* in_sizes, int n_in,
                              void* d_out, int out_size) {
    const float* feat   = (const float*)d_in[0];
    const int*   coords = (const int*)d_in[1];
    int N = in_sizes[1] / 4;
    int C = in_sizes[0] / N;          // 128
    if (N > MAXN) N = MAXN;           // safety (setup gives exactly 300000)

    float* out = (float*)d_out;
    size_t Ns = (size_t)N, Cs = (size_t)C;
    size_t off = Ns * Cs;             // feat at 0
    size_t off_keep = off; off += Ns;
    size_t off_w0   = off; off += Ns;
    size_t off_w1   = off; off += Ns;
    size_t off_dl0  = off; off += Ns;
    size_t off_dl1  = off; off += Ns;
    size_t off_i0   = off; off += Ns;
    size_t off_i1   = off; off += Ns;
    size_t off_pe0  = off; off += Ns * Cs;
    size_t off_pe1  = off;

    k_zerocnt<<<(NWc + 255) / 256, 256>>>();
    k_scatter0<<<592, 256>>>(coords, N);
    k_wrank0s1<<<NWc, 64>>>();
    k_wrank1<<<NWc, 64>>>();
    k_outvec<<<512, 256>>>(out, N, off_keep, off_w0, off_w1,
                           off_dl0, off_dl1, off_i0, off_i1);
    if ((N & 3) == 0 && (C == 128)) {
        k_outfeat_v4<<<2368, 128>>>(feat, coords, out, N, C, off_pe0, off_pe1);
    } else {
        k_outfeat_s<<<2368, 128>>>(feat, coords, out, N, C, off_pe0, off_pe1);
    }
}

// round 13
// speedup vs baseline: 2.3718x; 1.1735x over previous
#include <cuda_runtime.h>
#include <stdint.h>

// ---------------- problem constants ----------------
// SPARSE_SHAPE (468,468,1), WINDOW (12,12,1), BATCH 4
// _NX=_NY=40, _NZ=2 ; win_z==0 always ; full_win = 2*compact
// compact win id = b*1600 + wx*40 + wy  in [0, 6400)
#define NWc   6400
#define CAP   512               // max voxels per window (uniform data: ~49 mean)
#define MAXN  327680
#define FULLM 0xFFFFFFFFu
#define KLOG  0.4152410118609203f   // 4*log2(1e4)/128

// ---------------- static scratch (no allocations allowed) -------------------
__device__ int           g_cnt0[NWc];
__device__ int           g_cnt1[NWc];
__device__ int           g_bkt0[NWc * CAP];
__device__ int           g_bkt1[NWc * CAP];
__device__ int           g_winc0[MAXN];
__device__ int           g_winc1[MAXN];
__device__ int           g_inner0[MAXN];
__device__ int           g_inner1[MAXN];
__device__ unsigned char g_keep0[MAXN];
__device__ unsigned char g_keepF[MAXN];

__device__ __forceinline__ void lvl_target(int n, int& lvl, int& target) {
    if (n < 16)      { lvl = 0; target = 16; }
    else if (n < 32) { lvl = 1; target = 32; }
    else if (n < 64) { lvl = 2; target = 64; }
    else             { lvl = 3; target = 144; }
}

// ---------------- phase 0: zero the 2x6400 window counters ------------------
__global__ void k_zerocnt() {
    int i = blockIdx.x * blockDim.x + threadIdx.x;
    if (i < NWc) { g_cnt0[i] = 0; g_cnt1[i] = 0; }
}

// ---------------- phase 1: window ids + bucket scatter (round 0) ------------
__global__ void k_scatter0(const int* __restrict__ coords, int N) {
    int i = blockIdx.x * blockDim.x + threadIdx.x;
    if (i < N) {
        int4 cc = ((const int4*)coords)[i];          // (b,z,y,x)
        int b = cc.x, y = cc.z, x = cc.w;
        int w0 = b * 1600 + ((x + 12) / 12) * 40 + ((y + 12) / 12);
        int w1 = b * 1600 + ((x + 6)  / 12) * 40 + ((y + 6)  / 12);
        g_winc0[i] = w0;
        g_winc1[i] = w1;
        int pos = atomicAdd(&g_cnt0[w0], 1);
        if (pos < CAP) g_bkt0[w0 * CAP + pos] = i;
    }
}

// ---------------- phase 2: rank round 0 + inline scatter to round-1 buckets -
__global__ void __launch_bounds__(64)
k_wrank0s1() {
    __shared__ int s[CAP];
    int w = blockIdx.x;
    int n = g_cnt0[w];
    if (n > CAP) n = CAP;
    for (int t = threadIdx.x; t < n; t += 64) s[t] = g_bkt0[w * CAP + t];
    __syncthreads();
    int lvl, target; lvl_target(n, lvl, target);
    for (int e = threadIdx.x; e < n; e += 64) {
        int my = s[e];
        int r = 0;
        for (int j = 0; j < n; j++) r += (s[j] < my);
        g_inner0[my] = r;
        int kp = (r < target);
        g_keep0[my] = kp;
        if (kp) {
            int w1 = g_winc1[my];
            int pos = atomicAdd(&g_cnt1[w1], 1);
            if (pos < CAP) g_bkt1[w1 * CAP + pos] = my;
        } else {
            g_inner1[my] = -1;
            g_keepF[my]  = 0;
        }
    }
}

// ---------------- phase 3: per-window stable rank (round 1) -----------------
__global__ void __launch_bounds__(64)
k_wrank1() {
    __shared__ int s[CAP];
    int w = blockIdx.x;
    int n = g_cnt1[w];
    if (n > CAP) n = CAP;
    for (int t = threadIdx.x; t < n; t += 64) s[t] = g_bkt1[w * CAP + t];
    __syncthreads();
    int lvl, target; lvl_target(n, lvl, target);
    for (int e = threadIdx.x; e < n; e += 64) {
        int my = s[e];
        int r = 0;
        for (int j = 0; j < n; j++) r += (s[j] < my);
        g_inner1[my] = r;
        g_keepF[my]  = (r < target) ? 1 : 0;
    }
}

// ---------------- branch B: positional embeddings, SHORT blocks -------------
// One block = exactly 4 rows (warp per row), then exit. Short blocks recycle
// SM slots every ~1us so the concurrent aux chain co-schedules immediately.
// Lane l (l<16: x-half, else y-half) covers channels 4t..4t+3 (t=l&15):
// freqs 2t (sin,cos) and 2t+1 (sin,cos). Direct MUFU — no LUT, no smem.
__global__ void __launch_bounds__(128)
k_pe4(const int* __restrict__ coords, float* __restrict__ out, int N,
      size_t off_pe0, size_t off_pe1) {
    int warp = threadIdx.x >> 5, lane = threadIdx.x & 31;
    int i = blockIdx.x * 4 + warp;
    if (i >= N) return;
    int t = lane & 15;
    float rec0 = exp2f(-(float)(2 * t)     * KLOG);
    float rec1 = exp2f(-(float)(2 * t + 1) * KLOG);

    int x = __ldg(&coords[i * 4 + 3]);
    int y = __ldg(&coords[i * 4 + 2]);
    int v = (lane < 16) ? x : y;
    float v0 = (float)(v % 12) - 6.0f;
    float v1 = (float)((v + 6) % 12) - 6.0f;

    float4 p0, p1; float a;
    a = v0 * rec0; p0.x = __sinf(a); p0.y = __cosf(a);
    a = v0 * rec1; p0.z = __sinf(a); p0.w = __cosf(a);
    a = v1 * rec0; p1.x = __sinf(a); p1.y = __cosf(a);
    a = v1 * rec1; p1.z = __sinf(a); p1.w = __cosf(a);

    size_t row4 = (size_t)i * 32 + lane;
    ((float4*)(out + off_pe0))[row4] = p0;
    ((float4*)(out + off_pe1))[row4] = p1;
}

// ---------------- final: feat mask (vector) + scalar vectors, block-split ---
// Blocks [0,Gv): warp-per-row float4 feat masking (grid-stride).
// Blocks [Gv,..): flat one-thread-per-voxel scalar outputs.
// Split is at BLOCK granularity — control flow uniform inside each block.
__global__ void __launch_bounds__(128)
k_featvec(const float* __restrict__ feat, float* __restrict__ out, int N, int Gv,
          size_t off_keep, size_t off_w0, size_t off_w1,
          size_t off_dl0, size_t off_dl1, size_t off_i0, size_t off_i1) {
    if (blockIdx.x < (unsigned)Gv) {
        int warp = threadIdx.x >> 5, lane = threadIdx.x & 31;
        for (int i = blockIdx.x * 4 + warp; i < N; i += Gv * 4) {
            float kf = g_keepF[i] ? 1.0f : 0.0f;
            size_t row4 = (size_t)i * 32 + lane;
            float4 f = ((const float4*)feat)[row4];
            f.x *= kf; f.y *= kf; f.z *= kf; f.w *= kf;
            ((float4*)out)[row4] = f;
        }
    } else {
        int nb = gridDim.x - Gv;
        for (int i = (blockIdx.x - Gv) * 128 + threadIdx.x; i < N; i += nb * 128) {
            int w0 = g_winc0[i], w1 = g_winc1[i];
            out[off_keep + i] = g_keepF[i] ? 1.0f : 0.0f;
            out[off_w0 + i]   = (float)(2 * w0);
            out[off_w1 + i]   = (float)(2 * w1);
            int l0, t0; lvl_target(g_cnt0[w0], l0, t0);
            out[off_dl0 + i] = (float)l0;
            float dl1 = -1.0f;
            if (g_keep0[i]) {
                int l1, t1; lvl_target(g_cnt1[w1], l1, t1);
                dl1 = (float)l1;
            }
            out[off_dl1 + i] = dl1;
            out[off_i0 + i] = (float)g_inner0[i];
            out[off_i1 + i] = (float)g_inner1[i];
        }
    }
}

// ---------------- launch ----------------
extern "C" void kernel_launch(void* const* d_in, const int* in_sizes, int n_in,
                              void* d_out, int out_size) {
    const float* feat   = (const float*)d_in[0];
    const int*   coords = (const int*)d_in[1];
    int N = in_sizes[1] / 4;
    int C = in_sizes[0] / N;          // 128 (layout constants assume this)
    if (N > MAXN) N = MAXN;

    float* out = (float*)d_out;
    size_t Ns = (size_t)N, Cs = (size_t)C;
    size_t off = Ns * Cs;             // feat at 0
    size_t off_keep = off; off += Ns;
    size_t off_w0   = off; off += Ns;
    size_t off_w1   = off; off += Ns;
    size_t off_dl0  = off; off += Ns;
    size_t off_dl1  = off; off += Ns;
    size_t off_i0   = off; off += Ns;
    size_t off_i1   = off; off += Ns;
    size_t off_pe0  = off; off += Ns * Cs;
    size_t off_pe1  = off;

    // Fork: aux chain on HIGH-priority s2; short-block PE on the captured
    // stream. Short PE blocks free SM slots constantly, so aux co-schedules.
    int prLow = 0, prHigh = 0;
    cudaDeviceGetStreamPriorityRange(&prLow, &prHigh);
    cudaStream_t s2;
    cudaStreamCreateWithPriority(&s2, cudaStreamNonBlocking, prHigh);
    cudaEvent_t eFork, eJoin;
    cudaEventCreateWithFlags(&eFork, cudaEventDisableTiming);
    cudaEventCreateWithFlags(&eJoin, cudaEventDisableTiming);

    cudaEventRecord(eFork, 0);
    cudaStreamWaitEvent(s2, eFork, 0);

    // branch A (s2, high prio): rank chain + dependent outputs
    k_zerocnt<<<(NWc + 255) / 256, 256, 0, s2>>>();
    k_scatter0<<<(N + 255) / 256, 256, 0, s2>>>(coords, N);
    k_wrank0s1<<<NWc, 64, 0, s2>>>();
    k_wrank1<<<NWc, 64, 0, s2>>>();
    int Gv = 1184;                    // vector blocks; + 592 scalar blocks
    k_featvec<<<Gv + 592, 128, 0, s2>>>(feat, out, N, Gv,
                                        off_keep, off_w0, off_w1,
                                        off_dl0, off_dl1, off_i0, off_i1);

    // branch B (captured stream): PE, short blocks
    k_pe4<<<(N + 3) / 4, 128>>>(coords, out, N, off_pe0, off_pe1);

    cudaEventRecord(eJoin, s2);
    cudaStreamWaitEvent(0, eJoin, 0);   // join: stream 0 completes only when
                                        // both PE and the aux chain are done
    // s2/events deliberately not destroyed: destroying capture-participating
    // resources invalidates the graph; kernel_launch runs only a few times.
}